// round 11
// baseline (speedup 1.0000x reference)
#include <cuda_runtime.h>
#include <cstdint>

#define BS   256
#define SEQ  512
#define H    768

// Scratch (no allocations allowed)
__device__ float g_emb[BS * H];           // gathered "embraced" rows
__device__ float g_p0[BS][12];            // partial energies per n-tile
__device__ float g_p1[BS][12];

// ---------------------------------------------------------------------------
// Threefry-2x32, 20 rounds, key = (0, 42), partitionable scheme:
//   bits32(i) = x0 ^ x1 of threefry2x32(key, (0, i))
// ---------------------------------------------------------------------------
__device__ __forceinline__ uint32_t rotl32(uint32_t x, int r) {
    return (x << r) | (x >> (32 - r));
}

__device__ __forceinline__ uint32_t threefry_bits_partitionable(uint32_t i) {
    const uint32_t k0 = 0u, k1 = 42u;
    const uint32_t ks2 = 0x1BD11BDAu ^ k0 ^ k1;
    uint32_t x0 = 0u + k0;
    uint32_t x1 = i  + k1;

#define TF_BLOCK(r0_, r1_, r2_, r3_)                                   \
    x0 += x1; x1 = rotl32(x1, r0_); x1 ^= x0;                          \
    x0 += x1; x1 = rotl32(x1, r1_); x1 ^= x0;                          \
    x0 += x1; x1 = rotl32(x1, r2_); x1 ^= x0;                          \
    x0 += x1; x1 = rotl32(x1, r3_); x1 ^= x0;

    TF_BLOCK(13, 15, 26, 6)   x0 += k1;  x1 += ks2 + 1u;
    TF_BLOCK(17, 29, 16, 24)  x0 += ks2; x1 += k0  + 2u;
    TF_BLOCK(13, 15, 26, 6)   x0 += k0;  x1 += k1  + 3u;
    TF_BLOCK(17, 29, 16, 24)  x0 += k1;  x1 += ks2 + 4u;
    TF_BLOCK(13, 15, 26, 6)   x0 += ks2; x1 += k0  + 5u;
#undef TF_BLOCK
    return x0 ^ x1;
}

// fast tanh via MUFU.EX2: exact limits at +-inf
__device__ __forceinline__ float fast_tanh(float x) {
    return 1.0f - 2.0f / (__expf(2.0f * x) + 1.0f);
}

// ---------------------------------------------------------------------------
// Kernel 1: fused length-scan + gather. One block per batch, 384 threads,
// 2 elements per thread, L2-only gather loads. (At random-DRAM ceiling.)
// ---------------------------------------------------------------------------
__global__ void __launch_bounds__(384, 4)
prep_kernel(const float* __restrict__ tokens,
            const int*   __restrict__ mask) {
    const int b   = blockIdx.x;
    const int tid = threadIdx.x;   // 0..383

    __shared__ int s_len;
    if (tid == 0) s_len = SEQ;
    __syncthreads();
    if (mask[b * SEQ + tid] == 0) atomicMin(&s_len, tid);
    {
        const int t2 = tid + 384;
        if (t2 < SEQ && mask[b * SEQ + t2] == 0) atomicMin(&s_len, t2);
    }
    __syncthreads();
    const int   len  = s_len;
    const float lenf = (float)len;

    const int j0 = tid * 2;
    const int i0 = b * H + j0;

    const uint32_t bits0 = threefry_bits_partitionable((uint32_t)i0);
    const uint32_t bits1 = threefry_bits_partitionable((uint32_t)(i0 + 1));
    const float u0 = __uint_as_float((bits0 >> 9) | 0x3f800000u) - 1.0f;
    const float u1 = __uint_as_float((bits1 >> 9) | 0x3f800000u) - 1.0f;
    int idx0 = (int)floorf(u0 * lenf);
    int idx1 = (int)floorf(u1 * lenf);
    if (idx0 > len - 1) idx0 = len - 1;
    if (idx1 > len - 1) idx1 = len - 1;

    const size_t rowb = (size_t)b * SEQ * H;
    const float e0 = __ldcg(&tokens[rowb + (size_t)idx0 * H + j0]);
    const float e1 = __ldcg(&tokens[rowb + (size_t)idx1 * H + j0 + 1]);
    *reinterpret_cast<float2*>(&g_emb[i0]) = make_float2(e0, e1);
}

// ---------------------------------------------------------------------------
// Kernel 2: fused TF32 GEMM + energy.
// Each block (BM=32 x BN=64) computes, over full K=768:
//   acc0 = cls@Wtop, acc1 = cls@Wbot, acc2 = emb@Wbot
// then reduces  p0 = sum_j tanh(acc0+acc1+b)*v,  p1 = sum_j tanh(acc0+acc2+b)*v
// over its 64 columns and writes per-n-tile partials. No g_S round trip.
// Grid (12 n-tiles, 8 m-tiles) = 96 blocks, 256 threads (8 warps, 2m x 4n).
// ---------------------------------------------------------------------------
#define BK     16
#define NIT    (H / BK)   // 48
#define NSTAGE 3
#define APAD   20
#define BPAD   72
#define A_W    (32 * APAD)      // 640  words per A matrix per stage
#define B_W    (BK * BPAD)      // 1152 words per B matrix per stage
#define STG_A  (2 * A_W)        // cls + emb
#define STG_B  (2 * B_W)        // Wtop + Wbot

__device__ __forceinline__ void cp16(uint32_t saddr, const void* gaddr) {
    asm volatile("cp.async.ca.shared.global [%0], [%1], 16;\n"
                 :: "r"(saddr), "l"(gaddr));
}
__device__ __forceinline__ void cp8(uint32_t saddr, const void* gaddr) {
    asm volatile("cp.async.ca.shared.global [%0], [%1], 8;\n"
                 :: "r"(saddr), "l"(gaddr));
}
__device__ __forceinline__ void cp_commit() {
    asm volatile("cp.async.commit_group;\n");
}
template <int N>
__device__ __forceinline__ void cp_wait() {
    asm volatile("cp.async.wait_group %0;\n" :: "n"(N));
}

__device__ __forceinline__ void mma_tf32(float* d, const uint32_t* a, const uint32_t* b) {
    asm volatile(
        "mma.sync.aligned.m16n8k8.row.col.f32.tf32.tf32.f32 "
        "{%0,%1,%2,%3}, {%4,%5,%6,%7}, {%8,%9}, {%0,%1,%2,%3};\n"
        : "+f"(d[0]), "+f"(d[1]), "+f"(d[2]), "+f"(d[3])
        : "r"(a[0]), "r"(a[1]), "r"(a[2]), "r"(a[3]), "r"(b[0]), "r"(b[1]));
}

__global__ void __launch_bounds__(256, 1)
gemm_energy_kernel(const float* __restrict__ cls,
                   const float* __restrict__ W,
                   const float* __restrict__ bias,
                   const float* __restrict__ v) {
    const int n0 = blockIdx.x * 64;     // 0..11 n-tiles
    const int m0 = blockIdx.y * 32;     // 0..7  m-tiles (batch rows)

    __shared__ uint32_t As[NSTAGE][STG_A];   // [stage][{cls,emb}][32*APAD]
    __shared__ uint32_t Bs[NSTAGE][STG_B];   // [stage][{Wtop,Wbot}][16*BPAD]
    __shared__ float s_p0[32][4], s_p1[32][4];

    const int tid   = threadIdx.x;
    const int warp  = tid >> 5;
    const int lane  = tid & 31;
    const int wm    = (warp & 1) * 16;   // 2 m warps
    const int wn    = (warp >> 1) * 16;  // 4 n warps
    const int nwarp = warp >> 1;
    const int grp   = lane >> 2;
    const int tig   = lane & 3;

    // per-thread bias/v for owned columns (independent, issued early)
    float bv[2][2], vv[2][2];
#pragma unroll
    for (int ni = 0; ni < 2; ni++) {
        const int col = n0 + wn + ni * 8 + tig * 2;
        bv[ni][0] = bias[col];     bv[ni][1] = bias[col + 1];
        vv[ni][0] = v[col];        vv[ni][1] = v[col + 1];
    }

    // staging mapping
    const int a_r = tid >> 3;            // 0..31
    const int a_c = (tid & 7) * 2;       // 0,2,..,14   (cp8)
    const int b_r = tid >> 4;            // 0..15
    const int b_c = (tid & 15) * 4;      // 0..60       (cp16)

    const float* acls = &cls[(m0 + a_r) * H + a_c];
    const float* aemb = &g_emb[(m0 + a_r) * H + a_c];
    const float* wtop = &W[(size_t)b_r * H + n0 + b_c];
    const float* wbot = wtop + (size_t)H * H;

    const uint32_t smem0 = (uint32_t)__cvta_generic_to_shared(&As[0][0]);
    const uint32_t s_a0  = smem0 + (uint32_t)((a_r * APAD + a_c) * 4);
    const uint32_t s_b0  = (uint32_t)__cvta_generic_to_shared(&Bs[0][0]) +
                           (uint32_t)((b_r * BPAD + b_c) * 4);

    float acc0[2][4], acc1[2][4], acc2[2][4];
#pragma unroll
    for (int ni = 0; ni < 2; ni++)
#pragma unroll
        for (int r = 0; r < 4; r++) { acc0[ni][r] = 0.f; acc1[ni][r] = 0.f; acc2[ni][r] = 0.f; }

    // prologue: stages 0..1
#pragma unroll
    for (int s = 0; s < NSTAGE - 1; s++) {
        const uint32_t ao = (uint32_t)(s * STG_A * 4);
        const uint32_t bo = (uint32_t)(s * STG_B * 4);
        cp8 (s_a0 + ao,                         acls + s * BK);
        cp8 (s_a0 + ao + (uint32_t)(A_W * 4),   aemb + s * BK);
        cp16(s_b0 + bo,                         wtop + (size_t)(s * BK) * H);
        cp16(s_b0 + bo + (uint32_t)(B_W * 4),   wbot + (size_t)(s * BK) * H);
        cp_commit();
    }

    int buf = 0;
    for (int it = 0; it < NIT; it++) {
        cp_wait<NSTAGE - 2>();
        __syncthreads();

        const int nx = it + NSTAGE - 1;
        if (nx < NIT) {
            int nb = buf + (NSTAGE - 1); if (nb >= NSTAGE) nb -= NSTAGE;
            const uint32_t ao = (uint32_t)(nb * STG_A * 4);
            const uint32_t bo = (uint32_t)(nb * STG_B * 4);
            cp8 (s_a0 + ao,                       acls + nx * BK);
            cp8 (s_a0 + ao + (uint32_t)(A_W * 4), aemb + nx * BK);
            cp16(s_b0 + bo,                       wtop + (size_t)(nx * BK) * H);
            cp16(s_b0 + bo + (uint32_t)(B_W * 4), wbot + (size_t)(nx * BK) * H);
        }
        cp_commit();

        const uint32_t* Ac = &As[buf][0];          // cls tile
        const uint32_t* Ae = &As[buf][A_W];        // emb tile
        const uint32_t* Bt = &Bs[buf][0];          // Wtop tile
        const uint32_t* Bb = &Bs[buf][B_W];        // Wbot tile

#pragma unroll
        for (int ks = 0; ks < BK; ks += 8) {
            const int rbase = (wm + grp) * APAD + ks + tig;
            uint32_t ac[4], ae[4];
            ac[0] = Ac[rbase];            ac[1] = Ac[rbase + 8 * APAD];
            ac[2] = Ac[rbase + 4];        ac[3] = Ac[rbase + 8 * APAD + 4];
            ae[0] = Ae[rbase];            ae[1] = Ae[rbase + 8 * APAD];
            ae[2] = Ae[rbase + 4];        ae[3] = Ae[rbase + 8 * APAD + 4];

            uint32_t bt[2][2], bb[2][2];
#pragma unroll
            for (int ni = 0; ni < 2; ni++) {
                const int cbase = (ks + tig) * BPAD + wn + ni * 8 + grp;
                bt[ni][0] = Bt[cbase];    bt[ni][1] = Bt[cbase + 4 * BPAD];
                bb[ni][0] = Bb[cbase];    bb[ni][1] = Bb[cbase + 4 * BPAD];
            }
#pragma unroll
            for (int ni = 0; ni < 2; ni++) {
                mma_tf32(acc0[ni], ac, bt[ni]);   // cls @ Wtop
                mma_tf32(acc1[ni], ac, bb[ni]);   // cls @ Wbot
                mma_tf32(acc2[ni], ae, bb[ni]);   // emb @ Wbot
            }
        }
        if (++buf == NSTAGE) buf = 0;
    }

    // ---- in-register energy: rows wm+grp (ri=0) and wm+grp+8 (ri=1) ----
    float p0[2] = {0.f, 0.f}, p1[2] = {0.f, 0.f};
#pragma unroll
    for (int ri = 0; ri < 2; ri++) {
#pragma unroll
        for (int ni = 0; ni < 2; ni++) {
#pragma unroll
            for (int c = 0; c < 2; c++) {
                const int k = ri * 2 + c;
                const float s0 = acc0[ni][k];
                p0[ri] += fast_tanh(s0 + acc1[ni][k] + bv[ni][c]) * vv[ni][c];
                p1[ri] += fast_tanh(s0 + acc2[ni][k] + bv[ni][c]) * vv[ni][c];
            }
        }
    }
    // quad reduce over tig (lanes of a quad share grp)
#pragma unroll
    for (int off = 1; off <= 2; off <<= 1) {
#pragma unroll
        for (int ri = 0; ri < 2; ri++) {
            p0[ri] += __shfl_xor_sync(0xffffffffu, p0[ri], off);
            p1[ri] += __shfl_xor_sync(0xffffffffu, p1[ri], off);
        }
    }
    if (tig == 0) {
        s_p0[wm + grp][nwarp]     = p0[0];
        s_p0[wm + grp + 8][nwarp] = p0[1];
        s_p1[wm + grp][nwarp]     = p1[0];
        s_p1[wm + grp + 8][nwarp] = p1[1];
    }
    __syncthreads();
    if (tid < 32) {
        const float e0 = s_p0[tid][0] + s_p0[tid][1] + s_p0[tid][2] + s_p0[tid][3];
        const float e1 = s_p1[tid][0] + s_p1[tid][1] + s_p1[tid][2] + s_p1[tid][3];
        g_p0[m0 + tid][blockIdx.x] = e0;
        g_p1[m0 + tid][blockIdx.x] = e1;
    }
}

// ---------------------------------------------------------------------------
// Kernel 3: epilogue-lite. One block per batch, 768 threads.
// Sum 12 partials (fixed order) -> alpha -> combine.
// ---------------------------------------------------------------------------
__global__ void __launch_bounds__(768, 2)
epilogue_kernel(const float* __restrict__ cls,
                float*       __restrict__ out) {
    const int b   = blockIdx.x;
    const int tid = threadIdx.x;
    const size_t base = (size_t)b * H + tid;

    // prefetch streaming operands before the tiny reduction
    const float cv = cls[base];
    const float ev = g_emb[base];

    __shared__ float s_alpha;
    if (tid == 0) {
        float e0 = 0.f, e1 = 0.f;
#pragma unroll
        for (int i = 0; i < 12; i++) { e0 += g_p0[b][i]; e1 += g_p1[b][i]; }
        const float m  = fmaxf(e0, e1);
        const float w0 = __expf(e0 - m);
        const float w1 = __expf(e1 - m);
        s_alpha = w0 / (w0 + w1);
    }
    __syncthreads();
    const float a0 = s_alpha;
    out[base] = a0 * cv + (1.0f - a0) * ev;
}

// ---------------------------------------------------------------------------
// kernel_launch — inputs identified BY ELEMENT COUNT
// ---------------------------------------------------------------------------
extern "C" void kernel_launch(void* const* d_in, const int* in_sizes, int n_in,
                              void* d_out, int out_size) {
    const float* tokens = nullptr;
    const float* cls    = nullptr;
    const int*   mask   = nullptr;
    const float* W      = nullptr;
    const float* bias   = nullptr;
    const float* v      = nullptr;

    for (int i = 0; i < n_in; i++) {
        const int sz = in_sizes[i];
        if      (sz == BS * SEQ * H) tokens = (const float*)d_in[i];
        else if (sz == BS * H)       cls    = (const float*)d_in[i];
        else if (sz == BS * SEQ)     mask   = (const int*)  d_in[i];
        else if (sz == 2 * H * H)    W      = (const float*)d_in[i];
        else if (sz == H) {
            if (bias == nullptr)     bias   = (const float*)d_in[i];
            else                     v      = (const float*)d_in[i];
        }
    }
    float* out = (float*)d_out;

    prep_kernel<<<BS, 384>>>(tokens, mask);
    gemm_energy_kernel<<<dim3(12, 8), 256>>>(cls, W, bias, v);
    epilogue_kernel<<<BS, 768>>>(cls, out);
}

// round 12
// speedup vs baseline: 1.1794x; 1.1794x over previous
#include <cuda_runtime.h>
#include <cstdint>

#define BS   256
#define SEQ  512
#define H    768

// Scratch (no allocations allowed)
__device__ float g_emb[BS * H];          // gathered "embraced" rows
__device__ float g_S[3 * BS * H];        // S0 = cls@Wtop, S1 = cls@Wbot, S2 = emb@Wbot

// ---------------------------------------------------------------------------
// Threefry-2x32, 20 rounds, key = (0, 42), partitionable scheme:
//   bits32(i) = x0 ^ x1 of threefry2x32(key, (0, i))
// ---------------------------------------------------------------------------
__device__ __forceinline__ uint32_t rotl32(uint32_t x, int r) {
    return (x << r) | (x >> (32 - r));
}

__device__ __forceinline__ uint32_t threefry_bits_partitionable(uint32_t i) {
    const uint32_t k0 = 0u, k1 = 42u;
    const uint32_t ks2 = 0x1BD11BDAu ^ k0 ^ k1;
    uint32_t x0 = 0u + k0;
    uint32_t x1 = i  + k1;

#define TF_BLOCK(r0_, r1_, r2_, r3_)                                   \
    x0 += x1; x1 = rotl32(x1, r0_); x1 ^= x0;                          \
    x0 += x1; x1 = rotl32(x1, r1_); x1 ^= x0;                          \
    x0 += x1; x1 = rotl32(x1, r2_); x1 ^= x0;                          \
    x0 += x1; x1 = rotl32(x1, r3_); x1 ^= x0;

    TF_BLOCK(13, 15, 26, 6)   x0 += k1;  x1 += ks2 + 1u;
    TF_BLOCK(17, 29, 16, 24)  x0 += ks2; x1 += k0  + 2u;
    TF_BLOCK(13, 15, 26, 6)   x0 += k0;  x1 += k1  + 3u;
    TF_BLOCK(17, 29, 16, 24)  x0 += k1;  x1 += ks2 + 4u;
    TF_BLOCK(13, 15, 26, 6)   x0 += ks2; x1 += k0  + 5u;
#undef TF_BLOCK
    return x0 ^ x1;
}

// fast tanh via MUFU.EX2: exact limits at +-inf
__device__ __forceinline__ float fast_tanh(float x) {
    return 1.0f - 2.0f / (__expf(2.0f * x) + 1.0f);
}

// ---------------------------------------------------------------------------
// Kernel 1: fused length-scan + gather. One block per batch, 384 threads,
// 2 elements per thread, L2-only gather loads. (At random-DRAM ceiling.)
// ---------------------------------------------------------------------------
__global__ void __launch_bounds__(384, 4)
prep_kernel(const float* __restrict__ tokens,
            const int*   __restrict__ mask) {
    const int b   = blockIdx.x;
    const int tid = threadIdx.x;   // 0..383

    __shared__ int s_len;
    if (tid == 0) s_len = SEQ;
    __syncthreads();
    if (mask[b * SEQ + tid] == 0) atomicMin(&s_len, tid);
    {
        const int t2 = tid + 384;
        if (t2 < SEQ && mask[b * SEQ + t2] == 0) atomicMin(&s_len, t2);
    }
    __syncthreads();
    const int   len  = s_len;
    const float lenf = (float)len;

    const int j0 = tid * 2;
    const int i0 = b * H + j0;

    const uint32_t bits0 = threefry_bits_partitionable((uint32_t)i0);
    const uint32_t bits1 = threefry_bits_partitionable((uint32_t)(i0 + 1));
    const float u0 = __uint_as_float((bits0 >> 9) | 0x3f800000u) - 1.0f;
    const float u1 = __uint_as_float((bits1 >> 9) | 0x3f800000u) - 1.0f;
    int idx0 = (int)floorf(u0 * lenf);
    int idx1 = (int)floorf(u1 * lenf);
    if (idx0 > len - 1) idx0 = len - 1;
    if (idx1 > len - 1) idx1 = len - 1;

    const size_t rowb = (size_t)b * SEQ * H;
    const float e0 = __ldcg(&tokens[rowb + (size_t)idx0 * H + j0]);
    const float e1 = __ldcg(&tokens[rowb + (size_t)idx1 * H + j0 + 1]);
    *reinterpret_cast<float2*>(&g_emb[i0]) = make_float2(e0, e1);
}

// ---------------------------------------------------------------------------
// Kernel 2: TF32 GEMM. BM=64, BN=64, BK=32, double-buffered cp.async.
// g_S[g] = Xg @ Wg, g in {0,1,2}. Grid (12, 12) = 144 blocks, 256 threads.
// Raw f32 bits fed to mma.tf32 (top-19-bit truncation).
// ---------------------------------------------------------------------------
#define BK     32
#define NIT    (H / BK)   // 24
#define NSTAGE 2
#define APAD   36   // A row stride (words): frag banks = 4*grp + tig, distinct
#define BPAD   72   // B row stride (words): frag banks = 8*tig + grp, distinct
#define A_WORDS (64 * APAD)   // 2304
#define B_WORDS (BK * BPAD)   // 2304

__device__ __forceinline__ void cp16(uint32_t saddr, const void* gaddr) {
    asm volatile("cp.async.ca.shared.global [%0], [%1], 16;\n"
                 :: "r"(saddr), "l"(gaddr));
}
__device__ __forceinline__ void cp_commit() {
    asm volatile("cp.async.commit_group;\n");
}
template <int N>
__device__ __forceinline__ void cp_wait() {
    asm volatile("cp.async.wait_group %0;\n" :: "n"(N));
}

__device__ __forceinline__ void mma_tf32(float* d, const uint32_t* a, const uint32_t* b) {
    asm volatile(
        "mma.sync.aligned.m16n8k8.row.col.f32.tf32.tf32.f32 "
        "{%0,%1,%2,%3}, {%4,%5,%6,%7}, {%8,%9}, {%0,%1,%2,%3};\n"
        : "+f"(d[0]), "+f"(d[1]), "+f"(d[2]), "+f"(d[3])
        : "r"(a[0]), "r"(a[1]), "r"(a[2]), "r"(a[3]), "r"(b[0]), "r"(b[1]));
}

__global__ void __launch_bounds__(256, 1)
gemm_tf32_kernel(const float* __restrict__ cls,
                 const float* __restrict__ W) {
    const int g  = blockIdx.y >> 2;             // group 0..2
    const int m0 = (blockIdx.y & 3) * 64;
    const int n0 = blockIdx.x * 64;

    const float* __restrict__ A  = (g == 2) ? g_emb : cls;
    const float* __restrict__ Wg = W + (g == 0 ? 0 : (size_t)H * H);

    __shared__ uint32_t As[NSTAGE][A_WORDS];
    __shared__ uint32_t Bs[NSTAGE][B_WORDS];

    const int tid  = threadIdx.x;
    const int warp = tid >> 5;
    const int lane = tid & 31;
    const int wm   = (warp & 1) * 32;
    const int wn   = (warp >> 1) * 16;
    const int grp  = lane >> 2;
    const int tig  = lane & 3;

    // staging: A 64x32 floats -> 8/thread (2x cp16); B 32x64 -> 8/thread (2x cp16)
    const int a_r = tid >> 2;            // 0..63
    const int a_c = (tid & 3) * 8;       // 0,8,16,24
    const int b_r = tid >> 3;            // 0..31
    const int b_c = (tid & 7) * 8;       // 0,8,..,56

    const float* a_src = &A[(m0 + a_r) * H + a_c];
    const float* b_src = &Wg[(size_t)b_r * H + n0 + b_c];

    const uint32_t s_as = (uint32_t)__cvta_generic_to_shared(&As[0][0]) +
                          (uint32_t)((a_r * APAD + a_c) * 4);
    const uint32_t s_bs = (uint32_t)__cvta_generic_to_shared(&Bs[0][0]) +
                          (uint32_t)((b_r * BPAD + b_c) * 4);

    float acc[2][2][4];
#pragma unroll
    for (int mi = 0; mi < 2; mi++)
#pragma unroll
        for (int ni = 0; ni < 2; ni++)
#pragma unroll
            for (int r = 0; r < 4; r++) acc[mi][ni][r] = 0.0f;

    // prologue: stage 0
    cp16(s_as,      a_src);
    cp16(s_as + 16, a_src + 4);
    cp16(s_bs,      b_src);
    cp16(s_bs + 16, b_src + 4);
    cp_commit();

    for (int it = 0; it < NIT; it++) {
        cp_wait<0>();                    // tile `it` resident
        __syncthreads();                 // all warps done with tile it-1 (same buf as it+1)

        const int nx = it + 1;
        if (nx < NIT) {
            const uint32_t ao = (uint32_t)((nx & 1) * A_WORDS * 4);
            const uint32_t bo = (uint32_t)((nx & 1) * B_WORDS * 4);
            cp16(s_as + ao,      a_src + nx * BK);
            cp16(s_as + ao + 16, a_src + nx * BK + 4);
            cp16(s_bs + bo,      b_src + (size_t)(nx * BK) * H);
            cp16(s_bs + bo + 16, b_src + (size_t)(nx * BK) * H + 4);
        }
        cp_commit();

        const uint32_t* Asb = As[it & 1];
        const uint32_t* Bsb = Bs[it & 1];
#pragma unroll
        for (int ks = 0; ks < BK; ks += 8) {
            uint32_t afr[2][4];
#pragma unroll
            for (int mi = 0; mi < 2; mi++) {
                const int rbase = (wm + mi * 16 + grp) * APAD + ks + tig;
                afr[mi][0] = Asb[rbase];
                afr[mi][1] = Asb[rbase + 8 * APAD];
                afr[mi][2] = Asb[rbase + 4];
                afr[mi][3] = Asb[rbase + 8 * APAD + 4];
            }
            uint32_t bfr[2][2];
#pragma unroll
            for (int ni = 0; ni < 2; ni++) {
                const int cbase = (ks + tig) * BPAD + wn + ni * 8 + grp;
                bfr[ni][0] = Bsb[cbase];
                bfr[ni][1] = Bsb[cbase + 4 * BPAD];
            }
#pragma unroll
            for (int mi = 0; mi < 2; mi++)
#pragma unroll
                for (int ni = 0; ni < 2; ni++)
                    mma_tf32(acc[mi][ni], afr[mi], bfr[ni]);
        }
    }

    float* __restrict__ Cp = g_S + (size_t)g * BS * H;
#pragma unroll
    for (int mi = 0; mi < 2; mi++) {
#pragma unroll
        for (int ni = 0; ni < 2; ni++) {
            const int col = n0 + wn + ni * 8 + tig * 2;
            const int r0  = m0 + wm + mi * 16 + grp;
            *reinterpret_cast<float2*>(&Cp[(size_t)r0 * H + col]) =
                make_float2(acc[mi][ni][0], acc[mi][ni][1]);
            *reinterpret_cast<float2*>(&Cp[(size_t)(r0 + 8) * H + col]) =
                make_float2(acc[mi][ni][2], acc[mi][ni][3]);
        }
    }
}

// ---------------------------------------------------------------------------
// Kernel 3: fused epilogue. One block per batch, 768 threads.
// All loads up front; e_k = v . tanh(S0 + S_k + b); softmax; combine.
// ---------------------------------------------------------------------------
__global__ void __launch_bounds__(768, 2)
epilogue_kernel(const float* __restrict__ cls,
                const float* __restrict__ bias,
                const float* __restrict__ v,
                float*       __restrict__ out) {
    const int b   = blockIdx.x;
    const int tid = threadIdx.x;

    const size_t base = (size_t)b * H + tid;

    const float cv = cls[base];
    const float ev = g_emb[base];
    const float a  = g_S[base];
    const float bb = g_S[(size_t)BS * H + base];
    const float c  = g_S[(size_t)2 * BS * H + base];
    const float bi = bias[tid];
    const float vv = v[tid];

    float p0 = fast_tanh(a + bb + bi) * vv;
    float p1 = fast_tanh(a + c  + bi) * vv;

#pragma unroll
    for (int off = 16; off > 0; off >>= 1) {
        p0 += __shfl_down_sync(0xffffffffu, p0, off);
        p1 += __shfl_down_sync(0xffffffffu, p1, off);
    }
    __shared__ float r0[24], r1[24];
    __shared__ float s_alpha;
    const int w = tid >> 5, l = tid & 31;
    if (l == 0) { r0[w] = p0; r1[w] = p1; }
    __syncthreads();
    if (tid == 0) {
        float e0 = 0.0f, e1 = 0.0f;
#pragma unroll
        for (int i = 0; i < 24; i++) { e0 += r0[i]; e1 += r1[i]; }
        const float m  = fmaxf(e0, e1);
        const float w0 = __expf(e0 - m);
        const float w1 = __expf(e1 - m);
        s_alpha = w0 / (w0 + w1);
    }
    __syncthreads();
    const float a0 = s_alpha;
    out[base] = a0 * cv + (1.0f - a0) * ev;
}

// ---------------------------------------------------------------------------
// kernel_launch — inputs identified BY ELEMENT COUNT
// ---------------------------------------------------------------------------
extern "C" void kernel_launch(void* const* d_in, const int* in_sizes, int n_in,
                              void* d_out, int out_size) {
    const float* tokens = nullptr;
    const float* cls    = nullptr;
    const int*   mask   = nullptr;
    const float* W      = nullptr;
    const float* bias   = nullptr;
    const float* v      = nullptr;

    for (int i = 0; i < n_in; i++) {
        const int sz = in_sizes[i];
        if      (sz == BS * SEQ * H) tokens = (const float*)d_in[i];
        else if (sz == BS * H)       cls    = (const float*)d_in[i];
        else if (sz == BS * SEQ)     mask   = (const int*)  d_in[i];
        else if (sz == 2 * H * H)    W      = (const float*)d_in[i];
        else if (sz == H) {
            if (bias == nullptr)     bias   = (const float*)d_in[i];
            else                     v      = (const float*)d_in[i];
        }
    }
    float* out = (float*)d_out;

    prep_kernel<<<BS, 384>>>(tokens, mask);
    gemm_tf32_kernel<<<dim3(12, 12), 256>>>(cls, W);
    epilogue_kernel<<<BS, 768>>>(cls, bias, v, out);
}